// round 2
// baseline (speedup 1.0000x reference)
#include <cuda_runtime.h>

// MatchingLoss: B=64 batches, N=100000 points, 2D. Single fused kernel:
// grid-wide partial sums -> last-block finalize (threadfence + atomicInc trick).
// loss = 1000 * mean_b f( (mean||proj-img|| - mean||org-img||) / 1440 )
//   f(d) = ((1 + 5*relu(-d))*d + 5*relu(d)) / (1 + |d|)

#define BATCH   64
#define NPTS    100000
#define N4      (NPTS / 2)      // 50000 float4 per batch (2 points per float4)
#define CHUNKS  16
#define TOTAL_BLOCKS (BATCH * CHUNKS)
#define THREADS 256
#define DENOM   1440.0f

// Partial sums: [0 .. BATCH*CHUNKS): proj-img, [BATCH*CHUNKS .. 2*BATCH*CHUNKS): org-img.
// Written unconditionally every launch -> no zeroing needed.
__device__ float g_part[2 * BATCH * CHUNKS];
// Self-resetting completion counter: atomicInc with limit TOTAL_BLOCKS-1 wraps to 0
// after the last block, so state is identical before every graph replay.
__device__ unsigned int g_count;

__global__ __launch_bounds__(THREADS) void fused_kernel(
    const float4* __restrict__ img,
    const float4* __restrict__ proj,
    const float4* __restrict__ org,
    float* __restrict__ out)
{
    const int b     = blockIdx.x / CHUNKS;
    const int chunk = blockIdx.x % CHUNKS;
    const int per   = N4 / CHUNKS;            // 3125, exact
    const int start = chunk * per;
    const int end   = start + per;

    const float4* ib = img  + (size_t)b * N4;
    const float4* pb = proj + (size_t)b * N4;
    const float4* ob = org  + (size_t)b * N4;

    float s1 = 0.0f, s2 = 0.0f;
    #pragma unroll 2
    for (int i = start + threadIdx.x; i < end; i += THREADS) {
        float4 a = ib[i];
        float4 p = pb[i];
        float4 o = ob[i];
        float dx, dy;
        dx = p.x - a.x; dy = p.y - a.y; s1 += sqrtf(dx * dx + dy * dy);
        dx = p.z - a.z; dy = p.w - a.w; s1 += sqrtf(dx * dx + dy * dy);
        dx = o.x - a.x; dy = o.y - a.y; s2 += sqrtf(dx * dx + dy * dy);
        dx = o.z - a.z; dy = o.w - a.w; s2 += sqrtf(dx * dx + dy * dy);
    }

    // block reduce
    #pragma unroll
    for (int off = 16; off > 0; off >>= 1) {
        s1 += __shfl_down_sync(0xFFFFFFFFu, s1, off);
        s2 += __shfl_down_sync(0xFFFFFFFFu, s2, off);
    }
    __shared__ float sh1[THREADS / 32];
    __shared__ float sh2[THREADS / 32];
    const int lane = threadIdx.x & 31;
    const int wid  = threadIdx.x >> 5;
    if (lane == 0) { sh1[wid] = s1; sh2[wid] = s2; }
    __syncthreads();
    if (wid == 0) {
        s1 = (lane < THREADS / 32) ? sh1[lane] : 0.0f;
        s2 = (lane < THREADS / 32) ? sh2[lane] : 0.0f;
        #pragma unroll
        for (int off = 4; off > 0; off >>= 1) {
            s1 += __shfl_down_sync(0xFFFFFFFFu, s1, off);
            s2 += __shfl_down_sync(0xFFFFFFFFu, s2, off);
        }
        if (lane == 0) {
            g_part[b * CHUNKS + chunk] = s1;
            g_part[BATCH * CHUNKS + b * CHUNKS + chunk] = s2;
        }
    }

    // --- last-block finalize ---
    __shared__ bool is_last;
    __threadfence();                 // make partials visible before the count bump
    if (threadIdx.x == 0) {
        unsigned int prev = atomicInc(&g_count, TOTAL_BLOCKS - 1);  // wraps to 0 after last
        is_last = (prev == TOTAL_BLOCKS - 1);
    }
    __syncthreads();
    if (!is_last) return;
    __threadfence();                 // acquire side

    __shared__ float shf[BATCH];
    if (threadIdx.x < BATCH) {
        const int bb = threadIdx.x;
        float t1 = 0.0f, t2 = 0.0f;
        #pragma unroll
        for (int c = 0; c < CHUNKS; c++) {
            t1 += g_part[bb * CHUNKS + c];
            t2 += g_part[BATCH * CHUNKS + bb * CHUNKS + c];
        }
        const float inv = 1.0f / ((float)NPTS * DENOM);
        float d = (t1 - t2) * inv;
        float reward  = (1.0f + 5.0f * fmaxf(-d, 0.0f)) * d;
        float penalty = 5.0f * fmaxf(d, 0.0f);
        shf[bb] = (reward + penalty) / (1.0f + fabsf(d));
    }
    __syncthreads();
    if (threadIdx.x == 0) {
        float t = 0.0f;
        #pragma unroll
        for (int i = 0; i < BATCH; i++) t += shf[i];
        out[0] = 1000.0f * t / (float)BATCH;
    }
}

extern "C" void kernel_launch(void* const* d_in, const int* in_sizes, int n_in,
                              void* d_out, int out_size) {
    const float4* img  = (const float4*)d_in[0];
    const float4* proj = (const float4*)d_in[1];
    // d_in[2] = mat_reg_loss, unused by the reference computation
    const float4* org  = (const float4*)d_in[3];
    float* out = (float*)d_out;

    fused_kernel<<<TOTAL_BLOCKS, THREADS>>>(img, proj, org, out);
}

// round 3
// speedup vs baseline: 1.0164x; 1.0164x over previous
#include <cuda_runtime.h>

// MatchingLoss: B=64 batches, N=100000 points, 2D. Single fused kernel.
// Key R3 change: sqrtf -> d2 * rsqrtf(d2) (1 MUFU.RSQ + 1 FMUL) instead of
// the IEEE sqrt.rn expansion (~20 instr) that made R2 issue-bound.

#define BATCH   64
#define NPTS    100000
#define N4      (NPTS / 2)      // 50000 float4 per batch (2 points per float4)
#define CHUNKS  16
#define TOTAL_BLOCKS (BATCH * CHUNKS)
#define THREADS 256
#define DENOM   1440.0f

__device__ float g_part[2 * BATCH * CHUNKS];
__device__ unsigned int g_count;   // atomicInc wraps to 0 after last block -> replay-safe

__device__ __forceinline__ float fastdist(float dx, float dy) {
    float d2 = dx * dx + dy * dy;
    // d2 * rsqrt(d2) == sqrt(d2); fmax guard: d2==0 -> 0 * rsqrt(1e-38) == 0
    return d2 * rsqrtf(fmaxf(d2, 1e-38f));
}

__global__ __launch_bounds__(THREADS) void fused_kernel(
    const float4* __restrict__ img,
    const float4* __restrict__ proj,
    const float4* __restrict__ org,
    float* __restrict__ out)
{
    const int b     = blockIdx.x / CHUNKS;
    const int chunk = blockIdx.x % CHUNKS;
    const int per   = N4 / CHUNKS;            // 3125, exact
    const int start = chunk * per;
    const int end   = start + per;

    const float4* ib = img  + (size_t)b * N4;
    const float4* pb = proj + (size_t)b * N4;
    const float4* ob = org  + (size_t)b * N4;

    float s1 = 0.0f, s2 = 0.0f;
    #pragma unroll 4
    for (int i = start + threadIdx.x; i < end; i += THREADS) {
        float4 a = ib[i];
        float4 p = pb[i];
        float4 o = ob[i];
        s1 += fastdist(p.x - a.x, p.y - a.y);
        s1 += fastdist(p.z - a.z, p.w - a.w);
        s2 += fastdist(o.x - a.x, o.y - a.y);
        s2 += fastdist(o.z - a.z, o.w - a.w);
    }

    // block reduce
    #pragma unroll
    for (int off = 16; off > 0; off >>= 1) {
        s1 += __shfl_down_sync(0xFFFFFFFFu, s1, off);
        s2 += __shfl_down_sync(0xFFFFFFFFu, s2, off);
    }
    __shared__ float sh1[THREADS / 32];
    __shared__ float sh2[THREADS / 32];
    const int lane = threadIdx.x & 31;
    const int wid  = threadIdx.x >> 5;
    if (lane == 0) { sh1[wid] = s1; sh2[wid] = s2; }
    __syncthreads();
    if (wid == 0) {
        s1 = (lane < THREADS / 32) ? sh1[lane] : 0.0f;
        s2 = (lane < THREADS / 32) ? sh2[lane] : 0.0f;
        #pragma unroll
        for (int off = 4; off > 0; off >>= 1) {
            s1 += __shfl_down_sync(0xFFFFFFFFu, s1, off);
            s2 += __shfl_down_sync(0xFFFFFFFFu, s2, off);
        }
        if (lane == 0) {
            g_part[b * CHUNKS + chunk] = s1;
            g_part[BATCH * CHUNKS + b * CHUNKS + chunk] = s2;
        }
    }

    // --- last-block finalize ---
    __shared__ bool is_last;
    __threadfence();
    if (threadIdx.x == 0) {
        unsigned int prev = atomicInc(&g_count, TOTAL_BLOCKS - 1);
        is_last = (prev == TOTAL_BLOCKS - 1);
    }
    __syncthreads();
    if (!is_last) return;
    __threadfence();

    __shared__ float shf[BATCH];
    if (threadIdx.x < BATCH) {
        const int bb = threadIdx.x;
        float t1 = 0.0f, t2 = 0.0f;
        #pragma unroll
        for (int c = 0; c < CHUNKS; c++) {
            t1 += g_part[bb * CHUNKS + c];
            t2 += g_part[BATCH * CHUNKS + bb * CHUNKS + c];
        }
        const float inv = 1.0f / ((float)NPTS * DENOM);
        float d = (t1 - t2) * inv;
        float reward  = (1.0f + 5.0f * fmaxf(-d, 0.0f)) * d;
        float penalty = 5.0f * fmaxf(d, 0.0f);
        shf[bb] = (reward + penalty) / (1.0f + fabsf(d));
    }
    __syncthreads();
    if (threadIdx.x == 0) {
        float t = 0.0f;
        #pragma unroll
        for (int i = 0; i < BATCH; i++) t += shf[i];
        out[0] = 1000.0f * t / (float)BATCH;
    }
}

extern "C" void kernel_launch(void* const* d_in, const int* in_sizes, int n_in,
                              void* d_out, int out_size) {
    const float4* img  = (const float4*)d_in[0];
    const float4* proj = (const float4*)d_in[1];
    // d_in[2] = mat_reg_loss, unused by the reference computation
    const float4* org  = (const float4*)d_in[3];
    float* out = (float*)d_out;

    fused_kernel<<<TOTAL_BLOCKS, THREADS>>>(img, proj, org, out);
}

// round 4
// speedup vs baseline: 1.1941x; 1.1748x over previous
#include <cuda_runtime.h>

// MatchingLoss: B=64, N=100000, 2D. Single fused kernel.
// R4: single-wave grid (832 blocks <= 148 SMs * 6 blocks/SM) + unguarded
// unrolled-by-4 mainloop so ptxas can front-batch the 12 LDG.128s.

#define BATCH   64
#define NPTS    100000
#define N4      (NPTS / 2)       // 50000 float4 per batch
#define CHUNKS  13
#define TOTAL_BLOCKS (BATCH * CHUNKS)   // 832 -> single wave at 6 blocks/SM
#define THREADS 256
#define DENOM   1440.0f

__device__ float g_part[2 * BATCH * CHUNKS];
__device__ unsigned int g_count;   // atomicInc wraps to 0 after last block -> replay-safe

__device__ __forceinline__ float fastdist(float dx, float dy) {
    float d2 = dx * dx + dy * dy;
    return d2 * rsqrtf(fmaxf(d2, 1e-38f));   // == sqrt(d2); 0 -> 0
}

__device__ __forceinline__ void body(const float4 a, const float4 p, const float4 o,
                                     float& s1, float& s2) {
    s1 += fastdist(p.x - a.x, p.y - a.y);
    s1 += fastdist(p.z - a.z, p.w - a.w);
    s2 += fastdist(o.x - a.x, o.y - a.y);
    s2 += fastdist(o.z - a.z, o.w - a.w);
}

__global__ __launch_bounds__(THREADS) void fused_kernel(
    const float4* __restrict__ img,
    const float4* __restrict__ proj,
    const float4* __restrict__ org,
    float* __restrict__ out)
{
    const int b     = blockIdx.x / CHUNKS;
    const int chunk = blockIdx.x % CHUNKS;
    const int per   = (N4 + CHUNKS - 1) / CHUNKS;   // 3847
    const int start = chunk * per;
    const int end   = min(start + per, N4);
    const int span  = end - start;

    const float4* ib = img  + (size_t)b * N4;
    const float4* pb = proj + (size_t)b * N4;
    const float4* ob = org  + (size_t)b * N4;

    float s1 = 0.0f, s2 = 0.0f;

    // Main loop: uniform trip count per block, 12 unguarded LDG.128 per iter.
    const int n_full = span / (THREADS * 4);        // == 3 for every chunk
    int i = start + threadIdx.x;
    for (int k = 0; k < n_full; k++) {
        float4 a0 = ib[i];               float4 p0 = pb[i];               float4 o0 = ob[i];
        float4 a1 = ib[i +     THREADS]; float4 p1 = pb[i +     THREADS]; float4 o1 = ob[i +     THREADS];
        float4 a2 = ib[i + 2 * THREADS]; float4 p2 = pb[i + 2 * THREADS]; float4 o2 = ob[i + 2 * THREADS];
        float4 a3 = ib[i + 3 * THREADS]; float4 p3 = pb[i + 3 * THREADS]; float4 o3 = ob[i + 3 * THREADS];
        body(a0, p0, o0, s1, s2);
        body(a1, p1, o1, s1, s2);
        body(a2, p2, o2, s1, s2);
        body(a3, p3, o3, s1, s2);
        i += THREADS * 4;
    }
    // Tail (guarded, <= 4 iterations)
    for (; i < end; i += THREADS) {
        float4 a = ib[i]; float4 p = pb[i]; float4 o = ob[i];
        body(a, p, o, s1, s2);
    }

    // block reduce
    #pragma unroll
    for (int off = 16; off > 0; off >>= 1) {
        s1 += __shfl_down_sync(0xFFFFFFFFu, s1, off);
        s2 += __shfl_down_sync(0xFFFFFFFFu, s2, off);
    }
    __shared__ float sh1[THREADS / 32];
    __shared__ float sh2[THREADS / 32];
    const int lane = threadIdx.x & 31;
    const int wid  = threadIdx.x >> 5;
    if (lane == 0) { sh1[wid] = s1; sh2[wid] = s2; }
    __syncthreads();
    if (wid == 0) {
        s1 = (lane < THREADS / 32) ? sh1[lane] : 0.0f;
        s2 = (lane < THREADS / 32) ? sh2[lane] : 0.0f;
        #pragma unroll
        for (int off = 4; off > 0; off >>= 1) {
            s1 += __shfl_down_sync(0xFFFFFFFFu, s1, off);
            s2 += __shfl_down_sync(0xFFFFFFFFu, s2, off);
        }
        if (lane == 0) {
            g_part[b * CHUNKS + chunk] = s1;
            g_part[BATCH * CHUNKS + b * CHUNKS + chunk] = s2;
        }
    }

    // --- last-block finalize ---
    __shared__ bool is_last;
    __threadfence();
    if (threadIdx.x == 0) {
        unsigned int prev = atomicInc(&g_count, TOTAL_BLOCKS - 1);
        is_last = (prev == TOTAL_BLOCKS - 1);
    }
    __syncthreads();
    if (!is_last) return;
    __threadfence();

    __shared__ float shf[BATCH];
    if (threadIdx.x < BATCH) {
        const int bb = threadIdx.x;
        float t1 = 0.0f, t2 = 0.0f;
        #pragma unroll
        for (int c = 0; c < CHUNKS; c++) {
            t1 += g_part[bb * CHUNKS + c];
            t2 += g_part[BATCH * CHUNKS + bb * CHUNKS + c];
        }
        const float inv = 1.0f / ((float)NPTS * DENOM);
        float d = (t1 - t2) * inv;
        float reward  = (1.0f + 5.0f * fmaxf(-d, 0.0f)) * d;
        float penalty = 5.0f * fmaxf(d, 0.0f);
        shf[bb] = (reward + penalty) / (1.0f + fabsf(d));
    }
    __syncthreads();
    if (threadIdx.x == 0) {
        float t = 0.0f;
        #pragma unroll
        for (int i2 = 0; i2 < BATCH; i2++) t += shf[i2];
        out[0] = 1000.0f * t / (float)BATCH;
    }
}

extern "C" void kernel_launch(void* const* d_in, const int* in_sizes, int n_in,
                              void* d_out, int out_size) {
    const float4* img  = (const float4*)d_in[0];
    const float4* proj = (const float4*)d_in[1];
    // d_in[2] = mat_reg_loss, unused by the reference computation
    const float4* org  = (const float4*)d_in[3];
    float* out = (float*)d_out;

    fused_kernel<<<TOTAL_BLOCKS, THREADS>>>(img, proj, org, out);
}